// round 15
// baseline (speedup 1.0000x reference)
#include <cuda_runtime.h>
#include <cuda_fp16.h>
#include <cstdint>

#define DEV_INLINE __device__ __forceinline__

constexpr int B = 8, H = 128, W = 256, C = 128, D = 128;

__device__ float g_a[B * H * W];  // conv1(x) pre-relu
__device__ float g_s9[9];         // row-sums of w1 (for S field)

DEV_INLINE uint32_t smem_u32(const void* p) {
  uint32_t a;
  asm("{ .reg .u64 t; cvta.to.shared.u64 t, %1; cvt.u32.u64 %0, t; }" : "=r"(a) : "l"(p));
  return a;
}

// ============================================================
// Phase 1: register-tiled 1x9 conv, C->1. Thread = 8 px x 4 ch.
// Shuffle-tree reduction. Block (0,0,0) also emits s9 row-sums.
// ============================================================
constexpr int P1_TW = 64;
constexpr int P1_NC = 72;
constexpr int P1_XS = 132;

__global__ void __launch_bounds__(256, 4) phase1_kernel(const float* __restrict__ x,
                                                        const float* __restrict__ w1,
                                                        const float* __restrict__ b1) {
  __shared__ float xs[P1_NC * P1_XS];
  __shared__ float w1s[9 * C];
  const int w0 = blockIdx.x * P1_TW;
  const int h = blockIdx.y, b = blockIdx.z;
  const float* xrow = x + ((size_t)(b * H + h) * W) * C;
  const int tid = threadIdx.x;

#pragma unroll
  for (int u = 0; u < 2; u++) {
    int i = tid + u * 256;
    if (i < 9 * C / 4) ((float4*)w1s)[i] = ((const float4*)w1)[i];
  }

#pragma unroll 1
  for (int bb = 0; bb < 2; bb++) {
    float4 xv[5];
    int cols[5], c4s[5];
    const int nb = bb ? 4 : 5;
#pragma unroll
    for (int u = 0; u < 5; u++) {
      if (u < nb) {
        int idx = tid + (bb * 5 + u) * 256;
        int col = idx >> 5, c4 = idx & 31;
        cols[u] = col; c4s[u] = c4;
        int w = w0 - 4 + col;
        float4 v = make_float4(0.f, 0.f, 0.f, 0.f);
        if (w >= 0 && w < W) v = ((const float4*)(xrow + (size_t)w * C))[c4];
        xv[u] = v;
      }
    }
#pragma unroll
    for (int u = 0; u < 5; u++)
      if (u < nb) ((float4*)(xs + cols[u] * P1_XS))[c4s[u]] = xv[u];
  }
  __syncthreads();

  // one block computes s9 = row-sums of w1 (needed by phase-3's S field)
  if (w0 == 0 && h == 0 && b == 0 && tid < 9) {
    float acc = 0.f;
#pragma unroll 4
    for (int c = 0; c < C; c++) acc += w1s[tid * C + c];
    g_s9[tid] = acc;
  }

  const int cg = tid & 31, pxg = tid >> 5;   // lane = channel group, warp = pixel group
  const int c0 = cg * 4, p0 = pxg * 8;
  float wr[9][4];
#pragma unroll
  for (int k = 0; k < 9; k++)
#pragma unroll
    for (int c = 0; c < 4; c++) wr[k][c] = w1s[k * C + c0 + c];

  float acc[8];
#pragma unroll
  for (int i = 0; i < 8; i++) acc[i] = 0.f;

#pragma unroll
  for (int j = 0; j < 16; j++) {
    float4 xv = *(const float4*)(xs + (p0 + j) * P1_XS + c0);
#pragma unroll
    for (int pi = 0; pi < 8; pi++) {
      int kk = j - pi;
      if (kk >= 0 && kk < 9) {
        acc[pi] += xv.x * wr[kk][0] + xv.y * wr[kk][1] + xv.z * wr[kk][2] + xv.w * wr[kk][3];
      }
    }
  }
#pragma unroll
  for (int off = 16; off; off >>= 1)
#pragma unroll
    for (int pi = 0; pi < 8; pi++)
      acc[pi] += __shfl_xor_sync(0xffffffffu, acc[pi], off);
  if (cg == 0) {
    float bb = b1[0];
    float* dst = g_a + (size_t)(b * H + h) * W + w0 + p0;
    *(float4*)dst = make_float4(acc[0] + bb, acc[1] + bb, acc[2] + bb, acc[3] + bb);
    *(float4*)(dst + 4) = make_float4(acc[4] + bb, acc[5] + bb, acc[6] + bb, acc[7] + bb);
  }
}

// ============================================================
// Phase 3 (now also computes S inline): fp16 single-pass
// mma.sync, shadow-tile p scheme. 2 CTAs/SM.
// ============================================================
constexpr int WT3 = 128, NI3 = 130, MT3 = 144;
constexpr int ZB = 272;
constexpr int OFF_SCOL = 0;
constexpr int OFF_B2S = 520;
constexpr int OFF_Z1 = 1040;
constexpr int OFF_Z2 = OFF_Z1 + MT3 * ZB;      // 40208
constexpr int SM3_BYTES = OFF_Z2 + MT3 * ZB;   // 79376
constexpr int NT3 = 256;

DEV_INLINE void mma_f16(float acc[4], const uint32_t a[4], const uint32_t b[2]) {
  asm volatile(
      "mma.sync.aligned.m16n8k16.row.col.f32.f16.f16.f32 "
      "{%0,%1,%2,%3},{%4,%5,%6,%7},{%8,%9},{%0,%1,%2,%3};"
      : "+f"(acc[0]), "+f"(acc[1]), "+f"(acc[2]), "+f"(acc[3])
      : "r"(a[0]), "r"(a[1]), "r"(a[2]), "r"(a[3]), "r"(b[0]), "r"(b[1]));
}
DEV_INLINE void ldsm_x4(uint32_t r[4], uint32_t addr) {
  asm volatile("ldmatrix.sync.aligned.m8n8.x4.shared.b16 {%0,%1,%2,%3}, [%4];"
               : "=r"(r[0]), "=r"(r[1]), "=r"(r[2]), "=r"(r[3]) : "r"(addr));
}
DEV_INLINE uint32_t pack_h2(__half a, __half b) {
  __half2 t; t.x = a; t.y = b;
  return *reinterpret_cast<uint32_t*>(&t);
}
DEV_INLINE float2 rd2h(const char* smc, int off, int i, int n) {
  uint32_t hw = *(const uint32_t*)(smc + off + i * ZB + n * 2);
  __half2 hh = *reinterpret_cast<__half2*>(&hw);
  return make_float2(__half2float(hh.x), __half2float(hh.y));
}

DEV_INLINE void gemm_mt(uint32_t abase, const uint32_t bh[8][4][2], float accA[4][4]) {
#pragma unroll
  for (int kt = 0; kt < 8; kt++) {
    uint32_t ah[4];
    ldsm_x4(ah, abase + kt * 32);
#pragma unroll
    for (int ns = 0; ns < 4; ns++) {
      mma_f16(accA[ns], ah, bh[kt][ns]);
    }
  }
}

// one staging batch: 6 guarded LDG.128 then convert+store (fp16, Z1 only)
DEV_INLINE void stage_batch(char* smc, const float* __restrict__ xrow,
                            const float* scol, int tid, int w0, int batch) {
  float4 xv[6];
  int ii[6], cc[6];
#pragma unroll
  for (int u = 0; u < 6; u++) {
    int idx = tid + (batch * 6 + u) * NT3;
    int i = idx >> 5, c4 = idx & 31;
    ii[u] = i; cc[u] = c4;
    float4 v = make_float4(0.f, 0.f, 0.f, 0.f);
    if (i < NI3) {
      int J = (w0 - 2 + i) & (W - 1);
      v = *(const float4*)(xrow + (size_t)J * C + c4 * 4);
    }
    xv[u] = v;
  }
#pragma unroll
  for (int u = 0; u < 6; u++) {
    float sv = (ii[u] < NI3) ? scol[ii[u]] : 0.f;
    float4 v = xv[u];
    *(uint2*)(smc + OFF_Z1 + ii[u] * ZB + cc[u] * 8) =
        make_uint2(pack_h2(__float2half_rn(v.x + sv), __float2half_rn(v.y + sv)),
                   pack_h2(__float2half_rn(v.z + sv), __float2half_rn(v.w + sv)));
  }
}

__global__ void __launch_bounds__(NT3, 2) phase3_kernel(const float* __restrict__ x,
                                                        const float* __restrict__ w2g,
                                                        const float* __restrict__ b2g,
                                                        float* __restrict__ q) {
  extern __shared__ char smc[];
  const uint32_t sb = smem_u32(smc);
  float* scol = (float*)(smc + OFF_SCOL);
  float* b2s = (float*)(smc + OFF_B2S);

  const int tid = threadIdx.x;
  const int wid = tid >> 5, lane = tid & 31;
  const int w0 = blockIdx.x * WT3;
  const int h = blockIdx.y, b = blockIdx.z;
  const int gh = (h == 0 || h == H - 1) ? (H - 1) : ((h <= H - 3) ? h - 1 : H - 2);
  const float* xrow = x + ((size_t)(b * H + gh) * W) * C;
  const float* w2c = w2g + 4 * C * D;  // w2[0,4,:,:]

  // warp tiling: 4 n-groups x 2 m-groups; n=32 per warp
  const int g = lane >> 2, tig = lane & 3;
  const int ng = wid & 3, mg = wid >> 2;
  const int n0 = ng * 32;
  const int mt_lo = mg ? 5 : 0, mt_hi = mg ? 9 : 5;

  // B fragments from global first (longest-latency, overlap with everything)
  uint32_t bh[8][4][2];
#pragma unroll
  for (int kt = 0; kt < 8; kt++)
#pragma unroll
    for (int ns = 0; ns < 4; ns++) {
      int n = n0 + ns * 8 + g;
      int k = kt * 16 + tig * 2;
      float a0 = w2c[(size_t)k * D + n], a1 = w2c[(size_t)(k + 1) * D + n];
      float a2 = w2c[(size_t)(k + 8) * D + n], a3 = w2c[(size_t)(k + 9) * D + n];
      bh[kt][ns][0] = pack_h2(__float2half_rn(a0), __float2half_rn(a1));
      bh[kt][ns][1] = pack_h2(__float2half_rn(a2), __float2half_rn(a3));
    }

  // ---- S field computed inline (was phase-2), hidden under bh LDGs ----
  if (tid < NI3) {
    int J = (w0 - 2 + tid) & (W - 1);
    const float* ab = g_a + (size_t)b * H * W;
    float Sv;
    if (h == H - 1) {
      Sv = fmaxf(ab[(H - 2) * W + J], 0.f);
    } else {
      int hh = (h == H - 2) ? (H - 1) : h;
      float cy = ab[hh * W + J];
      if (hh >= 1) {
        const float* ap = ab + (hh - 1) * W;
#pragma unroll
        for (int k = 0; k < 9; k++) {
          int ww = J + k - 4;
          if (ww >= 0 && ww < W) cy += g_s9[k] * fmaxf(ap[ww], 0.f);
        }
      }
      float u = fmaxf(cy, 0.f);
      int tr = (h == 0) ? (H - 2) : (h == 1 ? -1 : (h <= H - 3 ? h - 2 : H - 3));
      Sv = u + ((tr >= 0) ? fmaxf(ab[tr * W + J], 0.f) : 0.f);
    }
    scol[tid] = Sv;
  }
  if (tid < 128) b2s[tid] = b2g[tid];
  __syncthreads();  // scol ready

  // stage z into Z1 in 3 MLP-6 batches (Z2 stays unstaged)
  stage_batch(smc, xrow, scol, tid, w0, 0);
  stage_batch(smc, xrow, scol, tid, w0, 1);
  stage_batch(smc, xrow, scol, tid, w0, 2);
  __syncthreads();

  const uint32_t aoff = (uint32_t)((lane & 15) * ZB + ((lane >> 4) << 4));

  // ---------- GEMM set 1 on Z1; epilogue writes p into Z2 ----------
#pragma unroll 1
  for (int mt = mt_lo; mt < mt_hi; mt++) {
    const int m0 = mt * 16;
    float accA[4][4] = {};
    gemm_mt(sb + OFF_Z1 + (uint32_t)(m0 * ZB) + aoff, bh, accA);
#pragma unroll
    for (int ns = 0; ns < 4; ns++) {
      int n = n0 + ns * 8 + tig * 2;
      float bb0 = b2s[n], bb1 = b2s[n + 1];
#pragma unroll
      for (int half = 0; half < 2; half++) {
        int r = m0 + g + half * 8;
        int t = r + 1;                       // p[t] = z[t] + v[r]
        if (t > 129) continue;
        float2 zz = rd2h(smc, OFF_Z1, t, n);
        if (!(w0 == 0 && t == 2)) {          // global col 0: p = z
          zz.x += fmaxf(accA[ns][half * 2] + bb0, 0.f);
          zz.y += fmaxf(accA[ns][half * 2 + 1] + bb1, 0.f);
        }
        *(uint32_t*)(smc + OFF_Z2 + t * ZB + n * 2) =
            pack_h2(__float2half_rn(zz.x), __float2half_rn(zz.y));
      }
    }
  }
  __syncthreads();

  // ---------- GEMM set 2 on Z2 (= p), fused q epilogue ----------
  float* qrow = q + ((size_t)(b * H + h) * W) * C;
#pragma unroll 1
  for (int mt = mt_lo; mt < mt_hi; mt++) {
    const int m0 = mt * 16;
    float accA[4][4] = {};
    gemm_mt(sb + OFF_Z2 + (uint32_t)(m0 * ZB) + aoff, bh, accA);
#pragma unroll
    for (int ns = 0; ns < 4; ns++) {
      int n = n0 + ns * 8 + tig * 2;
      float bb0 = b2s[n], bb1 = b2s[n + 1];
#pragma unroll
      for (int half = 0; half < 2; half++) {
        int i = m0 + g + half * 8;
        if (i < 2 || i >= NI3) continue;
        int w = w0 - 2 + i;
        if (w == W - 2) continue;  // r[W-2] discarded by the reference
        float r0 = fmaxf(accA[ns][half * 2] + bb0, 0.f);
        float r1 = fmaxf(accA[ns][half * 2 + 1] + bb1, 0.f);
        if (w == W - 1) {
          float2 p6 = rd2h(smc, OFF_Z2, i - 1, n);
          float2 p7 = rd2h(smc, OFF_Z2, i, n);
          *(float2*)(qrow + (size_t)(W - 2) * C + n) = make_float2(r0 + p6.x, r1 + p6.y);
          *(float2*)(qrow + (size_t)(W - 1) * C + n) = make_float2(p7.x, p7.y);
        } else {
          float2 pm = rd2h(smc, OFF_Z2, i - 1, n);
          *(float2*)(qrow + (size_t)w * C + n) = make_float2(r0 + pm.x, r1 + pm.y);
        }
      }
    }
  }
}

// ============================================================
extern "C" void kernel_launch(void* const* d_in, const int* in_sizes, int n_in,
                              void* d_out, int out_size) {
  (void)in_sizes; (void)n_in; (void)out_size;
  const float* x  = (const float*)d_in[0];
  const float* w1 = (const float*)d_in[1];
  const float* b1 = (const float*)d_in[2];
  const float* w2 = (const float*)d_in[3];
  const float* b2 = (const float*)d_in[4];
  float* q = (float*)d_out;

  cudaFuncSetAttribute(phase3_kernel, cudaFuncAttributeMaxDynamicSharedMemorySize, SM3_BYTES);

  phase1_kernel<<<dim3(W / P1_TW, H, B), 256>>>(x, w1, b1);
  phase3_kernel<<<dim3(W / WT3, H, B), NT3, SM3_BYTES>>>(x, w2, b2, q);
}

// round 16
// speedup vs baseline: 1.0832x; 1.0832x over previous
#include <cuda_runtime.h>
#include <cuda_fp16.h>
#include <cstdint>

#define DEV_INLINE __device__ __forceinline__

constexpr int B = 8, H = 128, W = 256, C = 128, D = 128;

__device__ float g_a[B * H * W];  // conv1(x) pre-relu
__device__ float g_s9[9];         // row-sums of w1 (for S field)

DEV_INLINE uint32_t smem_u32(const void* p) {
  uint32_t a;
  asm("{ .reg .u64 t; cvta.to.shared.u64 t, %1; cvt.u32.u64 %0, t; }" : "=r"(a) : "l"(p));
  return a;
}

// ============================================================
// Phase 1: register-tiled 1x9 conv, C->1 (proven; unchanged)
// ============================================================
constexpr int P1_TW = 64;
constexpr int P1_NC = 72;
constexpr int P1_XS = 132;

__global__ void __launch_bounds__(256, 4) phase1_kernel(const float* __restrict__ x,
                                                        const float* __restrict__ w1,
                                                        const float* __restrict__ b1) {
  __shared__ float xs[P1_NC * P1_XS];
  __shared__ float w1s[9 * C];
  const int w0 = blockIdx.x * P1_TW;
  const int h = blockIdx.y, b = blockIdx.z;
  const float* xrow = x + ((size_t)(b * H + h) * W) * C;
  const int tid = threadIdx.x;

#pragma unroll
  for (int u = 0; u < 2; u++) {
    int i = tid + u * 256;
    if (i < 9 * C / 4) ((float4*)w1s)[i] = ((const float4*)w1)[i];
  }

#pragma unroll 1
  for (int bb = 0; bb < 2; bb++) {
    float4 xv[5];
    int cols[5], c4s[5];
    const int nb = bb ? 4 : 5;
#pragma unroll
    for (int u = 0; u < 5; u++) {
      if (u < nb) {
        int idx = tid + (bb * 5 + u) * 256;
        int col = idx >> 5, c4 = idx & 31;
        cols[u] = col; c4s[u] = c4;
        int w = w0 - 4 + col;
        float4 v = make_float4(0.f, 0.f, 0.f, 0.f);
        if (w >= 0 && w < W) v = ((const float4*)(xrow + (size_t)w * C))[c4];
        xv[u] = v;
      }
    }
#pragma unroll
    for (int u = 0; u < 5; u++)
      if (u < nb) ((float4*)(xs + cols[u] * P1_XS))[c4s[u]] = xv[u];
  }
  __syncthreads();

  if (w0 == 0 && h == 0 && b == 0 && tid < 9) {
    float acc = 0.f;
#pragma unroll 4
    for (int c = 0; c < C; c++) acc += w1s[tid * C + c];
    g_s9[tid] = acc;
  }

  const int cg = tid & 31, pxg = tid >> 5;
  const int c0 = cg * 4, p0 = pxg * 8;
  float wr[9][4];
#pragma unroll
  for (int k = 0; k < 9; k++)
#pragma unroll
    for (int c = 0; c < 4; c++) wr[k][c] = w1s[k * C + c0 + c];

  float acc[8];
#pragma unroll
  for (int i = 0; i < 8; i++) acc[i] = 0.f;

#pragma unroll
  for (int j = 0; j < 16; j++) {
    float4 xv = *(const float4*)(xs + (p0 + j) * P1_XS + c0);
#pragma unroll
    for (int pi = 0; pi < 8; pi++) {
      int kk = j - pi;
      if (kk >= 0 && kk < 9) {
        acc[pi] += xv.x * wr[kk][0] + xv.y * wr[kk][1] + xv.z * wr[kk][2] + xv.w * wr[kk][3];
      }
    }
  }
#pragma unroll
  for (int off = 16; off; off >>= 1)
#pragma unroll
    for (int pi = 0; pi < 8; pi++)
      acc[pi] += __shfl_xor_sync(0xffffffffu, acc[pi], off);
  if (cg == 0) {
    float bb = b1[0];
    float* dst = g_a + (size_t)(b * H + h) * W + w0 + p0;
    *(float4*)dst = make_float4(acc[0] + bb, acc[1] + bb, acc[2] + bb, acc[3] + bb);
    *(float4*)(dst + 4) = make_float4(acc[4] + bb, acc[5] + bb, acc[6] + bb, acc[7] + bb);
  }
}

// ============================================================
// Phase 3: fp16 single-pass mma.sync, shadow-tile p, inline S.
//  3 CTAs/SM: 8n x 1m warps (bh=32 regs), smem 74.1KB via
//  Z2-before-Z1 layout (Z2 pad-row LDSM reads spill into Z1:
//  finite fp16 garbage, results discarded; row-independent mma).
// ============================================================
constexpr int WT3 = 128, NI3 = 130, MT3 = 144;
constexpr int ZB = 272;
constexpr int OFF_SCOL = 0;                    // 130 f32
constexpr int OFF_B2S = 520;                   // 128 f32 -> 1032, pad 1040
constexpr int OFF_Z2 = 1040;                   // 131 real rows
constexpr int OFF_Z1 = OFF_Z2 + 131 * ZB;      // 36672; 144 rows
constexpr int SM3_BYTES = OFF_Z1 + MT3 * ZB;   // 75840 (74.1KB)
constexpr int NT3 = 256;

DEV_INLINE void mma_f16(float acc[4], const uint32_t a[4], const uint32_t b[2]) {
  asm volatile(
      "mma.sync.aligned.m16n8k16.row.col.f32.f16.f16.f32 "
      "{%0,%1,%2,%3},{%4,%5,%6,%7},{%8,%9},{%0,%1,%2,%3};"
      : "+f"(acc[0]), "+f"(acc[1]), "+f"(acc[2]), "+f"(acc[3])
      : "r"(a[0]), "r"(a[1]), "r"(a[2]), "r"(a[3]), "r"(b[0]), "r"(b[1]));
}
DEV_INLINE void ldsm_x4(uint32_t r[4], uint32_t addr) {
  asm volatile("ldmatrix.sync.aligned.m8n8.x4.shared.b16 {%0,%1,%2,%3}, [%4];"
               : "=r"(r[0]), "=r"(r[1]), "=r"(r[2]), "=r"(r[3]) : "r"(addr));
}
DEV_INLINE uint32_t pack_h2(__half a, __half b) {
  __half2 t; t.x = a; t.y = b;
  return *reinterpret_cast<uint32_t*>(&t);
}
DEV_INLINE float2 rd2h(const char* smc, int off, int i, int n) {
  uint32_t hw = *(const uint32_t*)(smc + off + i * ZB + n * 2);
  __half2 hh = *reinterpret_cast<__half2*>(&hw);
  return make_float2(__half2float(hh.x), __half2float(hh.y));
}

DEV_INLINE void gemm_mt(uint32_t abase, const uint32_t bh[8][2][2], float accA[2][4]) {
#pragma unroll
  for (int kt = 0; kt < 8; kt++) {
    uint32_t ah[4];
    ldsm_x4(ah, abase + kt * 32);
#pragma unroll
    for (int ns = 0; ns < 2; ns++) {
      mma_f16(accA[ns], ah, bh[kt][ns]);
    }
  }
}

// one staging batch: NB guarded LDG.128 then convert+store (fp16, Z1)
template <int NB>
DEV_INLINE void stage_batch(char* smc, const float* __restrict__ xrow,
                            const float* scol, int tid, int w0, int start) {
  float4 xv[NB];
  int ii[NB], cc[NB];
#pragma unroll
  for (int u = 0; u < NB; u++) {
    int idx = tid + (start + u) * NT3;
    int i = idx >> 5, c4 = idx & 31;
    ii[u] = i; cc[u] = c4;
    float4 v = make_float4(0.f, 0.f, 0.f, 0.f);
    if (i < NI3) {
      int J = (w0 - 2 + i) & (W - 1);
      v = *(const float4*)(xrow + (size_t)J * C + c4 * 4);
    }
    xv[u] = v;
  }
#pragma unroll
  for (int u = 0; u < NB; u++) {
    float sv = (ii[u] < NI3) ? scol[ii[u]] : 0.f;
    float4 v = xv[u];
    *(uint2*)(smc + OFF_Z1 + ii[u] * ZB + cc[u] * 8) =
        make_uint2(pack_h2(__float2half_rn(v.x + sv), __float2half_rn(v.y + sv)),
                   pack_h2(__float2half_rn(v.z + sv), __float2half_rn(v.w + sv)));
  }
}

__global__ void __launch_bounds__(NT3, 3) phase3_kernel(const float* __restrict__ x,
                                                        const float* __restrict__ w2g,
                                                        const float* __restrict__ b2g,
                                                        float* __restrict__ q) {
  extern __shared__ char smc[];
  const uint32_t sb = smem_u32(smc);
  float* scol = (float*)(smc + OFF_SCOL);
  float* b2s = (float*)(smc + OFF_B2S);

  const int tid = threadIdx.x;
  const int wid = tid >> 5, lane = tid & 31;
  const int w0 = blockIdx.x * WT3;
  const int h = blockIdx.y, b = blockIdx.z;
  const int gh = (h == 0 || h == H - 1) ? (H - 1) : ((h <= H - 3) ? h - 1 : H - 2);
  const float* xrow = x + ((size_t)(b * H + gh) * W) * C;
  const float* w2c = w2g + 4 * C * D;  // w2[0,4,:,:]

  // 8 n-group warps, each covers all 9 m-tiles; n=16/warp
  const int g = lane >> 2, tig = lane & 3;
  const int n0 = wid * 16;

  // B fragments from global first (longest-latency, overlap with everything)
  uint32_t bh[8][2][2];
#pragma unroll
  for (int kt = 0; kt < 8; kt++)
#pragma unroll
    for (int ns = 0; ns < 2; ns++) {
      int n = n0 + ns * 8 + g;
      int k = kt * 16 + tig * 2;
      float a0 = w2c[(size_t)k * D + n], a1 = w2c[(size_t)(k + 1) * D + n];
      float a2 = w2c[(size_t)(k + 8) * D + n], a3 = w2c[(size_t)(k + 9) * D + n];
      bh[kt][ns][0] = pack_h2(__float2half_rn(a0), __float2half_rn(a1));
      bh[kt][ns][1] = pack_h2(__float2half_rn(a2), __float2half_rn(a3));
    }

  // ---- S field computed inline ----
  if (tid < NI3) {
    int J = (w0 - 2 + tid) & (W - 1);
    const float* ab = g_a + (size_t)b * H * W;
    float Sv;
    if (h == H - 1) {
      Sv = fmaxf(ab[(H - 2) * W + J], 0.f);
    } else {
      int hh = (h == H - 2) ? (H - 1) : h;
      float cy = ab[hh * W + J];
      if (hh >= 1) {
        const float* ap = ab + (hh - 1) * W;
#pragma unroll
        for (int k = 0; k < 9; k++) {
          int ww = J + k - 4;
          if (ww >= 0 && ww < W) cy += g_s9[k] * fmaxf(ap[ww], 0.f);
        }
      }
      float u = fmaxf(cy, 0.f);
      int tr = (h == 0) ? (H - 2) : (h == 1 ? -1 : (h <= H - 3 ? h - 2 : H - 3));
      Sv = u + ((tr >= 0) ? fmaxf(ab[tr * W + J], 0.f) : 0.f);
    }
    scol[tid] = Sv;
  }
  if (tid < 128) b2s[tid] = b2g[tid];
  __syncthreads();  // scol ready

  // stage z into Z1 in 4 MLP batches (5,5,4,4)
  stage_batch<5>(smc, xrow, scol, tid, w0, 0);
  stage_batch<5>(smc, xrow, scol, tid, w0, 5);
  stage_batch<4>(smc, xrow, scol, tid, w0, 10);
  stage_batch<4>(smc, xrow, scol, tid, w0, 14);
  __syncthreads();

  const uint32_t aoff = (uint32_t)((lane & 15) * ZB + ((lane >> 4) << 4));

  // ---------- GEMM set 1 on Z1; epilogue writes p into Z2 ----------
#pragma unroll 1
  for (int mt = 0; mt < 9; mt++) {
    const int m0 = mt * 16;
    float accA[2][4] = {};
    gemm_mt(sb + OFF_Z1 + (uint32_t)(m0 * ZB) + aoff, bh, accA);
#pragma unroll
    for (int ns = 0; ns < 2; ns++) {
      int n = n0 + ns * 8 + tig * 2;
      float bb0 = b2s[n], bb1 = b2s[n + 1];
#pragma unroll
      for (int half = 0; half < 2; half++) {
        int r = m0 + g + half * 8;
        int t = r + 1;                       // p[t] = z[t] + v[r]
        if (t > 129) continue;
        float2 zz = rd2h(smc, OFF_Z1, t, n);
        if (!(w0 == 0 && t == 2)) {          // global col 0: p = z
          zz.x += fmaxf(accA[ns][half * 2] + bb0, 0.f);
          zz.y += fmaxf(accA[ns][half * 2 + 1] + bb1, 0.f);
        }
        *(uint32_t*)(smc + OFF_Z2 + t * ZB + n * 2) =
            pack_h2(__float2half_rn(zz.x), __float2half_rn(zz.y));
      }
    }
  }
  __syncthreads();

  // ---------- GEMM set 2 on Z2 (= p), fused q epilogue ----------
  float* qrow = q + ((size_t)(b * H + h) * W) * C;
#pragma unroll 1
  for (int mt = 0; mt < 9; mt++) {
    const int m0 = mt * 16;
    float accA[2][4] = {};
    gemm_mt(sb + OFF_Z2 + (uint32_t)(m0 * ZB) + aoff, bh, accA);
#pragma unroll
    for (int ns = 0; ns < 2; ns++) {
      int n = n0 + ns * 8 + tig * 2;
      float bb0 = b2s[n], bb1 = b2s[n + 1];
#pragma unroll
      for (int half = 0; half < 2; half++) {
        int i = m0 + g + half * 8;
        if (i < 2 || i >= NI3) continue;
        int w = w0 - 2 + i;
        if (w == W - 2) continue;  // r[W-2] discarded by the reference
        float r0 = fmaxf(accA[ns][half * 2] + bb0, 0.f);
        float r1 = fmaxf(accA[ns][half * 2 + 1] + bb1, 0.f);
        if (w == W - 1) {
          float2 p6 = rd2h(smc, OFF_Z2, i - 1, n);
          float2 p7 = rd2h(smc, OFF_Z2, i, n);
          *(float2*)(qrow + (size_t)(W - 2) * C + n) = make_float2(r0 + p6.x, r1 + p6.y);
          *(float2*)(qrow + (size_t)(W - 1) * C + n) = make_float2(p7.x, p7.y);
        } else {
          float2 pm = rd2h(smc, OFF_Z2, i - 1, n);
          *(float2*)(qrow + (size_t)w * C + n) = make_float2(r0 + pm.x, r1 + pm.y);
        }
      }
    }
  }
}

// ============================================================
extern "C" void kernel_launch(void* const* d_in, const int* in_sizes, int n_in,
                              void* d_out, int out_size) {
  (void)in_sizes; (void)n_in; (void)out_size;
  const float* x  = (const float*)d_in[0];
  const float* w1 = (const float*)d_in[1];
  const float* b1 = (const float*)d_in[2];
  const float* w2 = (const float*)d_in[3];
  const float* b2 = (const float*)d_in[4];
  float* q = (float*)d_out;

  cudaFuncSetAttribute(phase3_kernel, cudaFuncAttributeMaxDynamicSharedMemorySize, SM3_BYTES);

  phase1_kernel<<<dim3(W / P1_TW, H, B), 256>>>(x, w1, b1);
  phase3_kernel<<<dim3(W / WT3, H, B), NT3, SM3_BYTES>>>(x, w2, b2, q);
}

// round 17
// speedup vs baseline: 1.1362x; 1.0490x over previous
#include <cuda_runtime.h>
#include <cuda_fp16.h>
#include <cstdint>

#define DEV_INLINE __device__ __forceinline__

constexpr int B = 8, H = 128, W = 256, C = 128, D = 128;

__device__ float g_a[B * H * W];  // conv1(x) pre-relu
__device__ float g_s9[9];         // row-sums of w1 (for S field)

DEV_INLINE uint32_t smem_u32(const void* p) {
  uint32_t a;
  asm("{ .reg .u64 t; cvta.to.shared.u64 t, %1; cvt.u32.u64 %0, t; }" : "=r"(a) : "l"(p));
  return a;
}

// ============================================================
// Phase 1: register-tiled 1x9 conv, C->1. Thread = 8 px x 4 ch.
// Staging now a single MLP-9 batch.
// ============================================================
constexpr int P1_TW = 64;
constexpr int P1_NC = 72;
constexpr int P1_XS = 132;

__global__ void __launch_bounds__(256, 4) phase1_kernel(const float* __restrict__ x,
                                                        const float* __restrict__ w1,
                                                        const float* __restrict__ b1) {
  __shared__ float xs[P1_NC * P1_XS];
  __shared__ float w1s[9 * C];
  const int w0 = blockIdx.x * P1_TW;
  const int h = blockIdx.y, b = blockIdx.z;
  const float* xrow = x + ((size_t)(b * H + h) * W) * C;
  const int tid = threadIdx.x;

#pragma unroll
  for (int u = 0; u < 2; u++) {
    int i = tid + u * 256;
    if (i < 9 * C / 4) ((float4*)w1s)[i] = ((const float4*)w1)[i];
  }

  // staging: one MLP-9 batch (loads fully issued before any store)
  {
    float4 xv[9];
#pragma unroll
    for (int u = 0; u < 9; u++) {
      int idx = tid + u * 256;
      int col = idx >> 5, c4 = idx & 31;
      int w = w0 - 4 + col;
      float4 v = make_float4(0.f, 0.f, 0.f, 0.f);
      if (w >= 0 && w < W) v = ((const float4*)(xrow + (size_t)w * C))[c4];
      xv[u] = v;
    }
#pragma unroll
    for (int u = 0; u < 9; u++) {
      int idx = tid + u * 256;
      int col = idx >> 5, c4 = idx & 31;
      ((float4*)(xs + col * P1_XS))[c4] = xv[u];
    }
  }
  __syncthreads();

  if (w0 == 0 && h == 0 && b == 0 && tid < 9) {
    float acc = 0.f;
#pragma unroll 4
    for (int c = 0; c < C; c++) acc += w1s[tid * C + c];
    g_s9[tid] = acc;
  }

  const int cg = tid & 31, pxg = tid >> 5;
  const int c0 = cg * 4, p0 = pxg * 8;
  float wr[9][4];
#pragma unroll
  for (int k = 0; k < 9; k++)
#pragma unroll
    for (int c = 0; c < 4; c++) wr[k][c] = w1s[k * C + c0 + c];

  float acc[8];
#pragma unroll
  for (int i = 0; i < 8; i++) acc[i] = 0.f;

#pragma unroll
  for (int j = 0; j < 16; j++) {
    float4 xv = *(const float4*)(xs + (p0 + j) * P1_XS + c0);
#pragma unroll
    for (int pi = 0; pi < 8; pi++) {
      int kk = j - pi;
      if (kk >= 0 && kk < 9) {
        acc[pi] += xv.x * wr[kk][0] + xv.y * wr[kk][1] + xv.z * wr[kk][2] + xv.w * wr[kk][3];
      }
    }
  }
#pragma unroll
  for (int off = 16; off; off >>= 1)
#pragma unroll
    for (int pi = 0; pi < 8; pi++)
      acc[pi] += __shfl_xor_sync(0xffffffffu, acc[pi], off);
  if (cg == 0) {
    float bb = b1[0];
    float* dst = g_a + (size_t)(b * H + h) * W + w0 + p0;
    *(float4*)dst = make_float4(acc[0] + bb, acc[1] + bb, acc[2] + bb, acc[3] + bb);
    *(float4*)(dst + 4) = make_float4(acc[4] + bb, acc[5] + bb, acc[6] + bb, acc[7] + bb);
  }
}

// ============================================================
// Phase 3: fp16 single-pass mma.sync, shadow-tile p, inline S.
//  3 CTAs/SM, Z2-before-Z1 layout. Staging now 2 MLP-9 batches.
// ============================================================
constexpr int WT3 = 128, NI3 = 130, MT3 = 144;
constexpr int ZB = 272;
constexpr int OFF_SCOL = 0;                    // 130 f32
constexpr int OFF_B2S = 520;                   // 128 f32 -> 1032, pad 1040
constexpr int OFF_Z2 = 1040;                   // 131 real rows
constexpr int OFF_Z1 = OFF_Z2 + 131 * ZB;      // 36672; 144 rows
constexpr int SM3_BYTES = OFF_Z1 + MT3 * ZB;   // 75840 (74.1KB)
constexpr int NT3 = 256;

DEV_INLINE void mma_f16(float acc[4], const uint32_t a[4], const uint32_t b[2]) {
  asm volatile(
      "mma.sync.aligned.m16n8k16.row.col.f32.f16.f16.f32 "
      "{%0,%1,%2,%3},{%4,%5,%6,%7},{%8,%9},{%0,%1,%2,%3};"
      : "+f"(acc[0]), "+f"(acc[1]), "+f"(acc[2]), "+f"(acc[3])
      : "r"(a[0]), "r"(a[1]), "r"(a[2]), "r"(a[3]), "r"(b[0]), "r"(b[1]));
}
DEV_INLINE void ldsm_x4(uint32_t r[4], uint32_t addr) {
  asm volatile("ldmatrix.sync.aligned.m8n8.x4.shared.b16 {%0,%1,%2,%3}, [%4];"
               : "=r"(r[0]), "=r"(r[1]), "=r"(r[2]), "=r"(r[3]) : "r"(addr));
}
DEV_INLINE uint32_t pack_h2(__half a, __half b) {
  __half2 t; t.x = a; t.y = b;
  return *reinterpret_cast<uint32_t*>(&t);
}
DEV_INLINE float2 rd2h(const char* smc, int off, int i, int n) {
  uint32_t hw = *(const uint32_t*)(smc + off + i * ZB + n * 2);
  __half2 hh = *reinterpret_cast<__half2*>(&hw);
  return make_float2(__half2float(hh.x), __half2float(hh.y));
}

DEV_INLINE void gemm_mt(uint32_t abase, const uint32_t bh[8][2][2], float accA[2][4]) {
#pragma unroll
  for (int kt = 0; kt < 8; kt++) {
    uint32_t ah[4];
    ldsm_x4(ah, abase + kt * 32);
#pragma unroll
    for (int ns = 0; ns < 2; ns++) {
      mma_f16(accA[ns], ah, bh[kt][ns]);
    }
  }
}

// one staging batch: NB guarded LDG.128 then convert+store (fp16, Z1)
template <int NB>
DEV_INLINE void stage_batch(char* smc, const float* __restrict__ xrow,
                            const float* scol, int tid, int w0, int start) {
  float4 xv[NB];
#pragma unroll
  for (int u = 0; u < NB; u++) {
    int idx = tid + (start + u) * NT3;
    int i = idx >> 5, c4 = idx & 31;
    float4 v = make_float4(0.f, 0.f, 0.f, 0.f);
    if (i < NI3) {
      int J = (w0 - 2 + i) & (W - 1);
      v = *(const float4*)(xrow + (size_t)J * C + c4 * 4);
    }
    xv[u] = v;
  }
#pragma unroll
  for (int u = 0; u < NB; u++) {
    int idx = tid + (start + u) * NT3;
    int i = idx >> 5, c4 = idx & 31;
    float sv = (i < NI3) ? scol[i] : 0.f;
    float4 v = xv[u];
    *(uint2*)(smc + OFF_Z1 + i * ZB + c4 * 8) =
        make_uint2(pack_h2(__float2half_rn(v.x + sv), __float2half_rn(v.y + sv)),
                   pack_h2(__float2half_rn(v.z + sv), __float2half_rn(v.w + sv)));
  }
}

__global__ void __launch_bounds__(NT3, 3) phase3_kernel(const float* __restrict__ x,
                                                        const float* __restrict__ w2g,
                                                        const float* __restrict__ b2g,
                                                        float* __restrict__ q) {
  extern __shared__ char smc[];
  const uint32_t sb = smem_u32(smc);
  float* scol = (float*)(smc + OFF_SCOL);
  float* b2s = (float*)(smc + OFF_B2S);

  const int tid = threadIdx.x;
  const int wid = tid >> 5, lane = tid & 31;
  const int w0 = blockIdx.x * WT3;
  const int h = blockIdx.y, b = blockIdx.z;
  const int gh = (h == 0 || h == H - 1) ? (H - 1) : ((h <= H - 3) ? h - 1 : H - 2);
  const float* xrow = x + ((size_t)(b * H + gh) * W) * C;
  const float* w2c = w2g + 4 * C * D;  // w2[0,4,:,:]

  // 8 n-group warps, each covers all 9 m-tiles; n=16/warp
  const int g = lane >> 2, tig = lane & 3;
  const int n0 = wid * 16;

  // B fragments from global first (longest-latency, overlap with everything)
  uint32_t bh[8][2][2];
#pragma unroll
  for (int kt = 0; kt < 8; kt++)
#pragma unroll
    for (int ns = 0; ns < 2; ns++) {
      int n = n0 + ns * 8 + g;
      int k = kt * 16 + tig * 2;
      float a0 = w2c[(size_t)k * D + n], a1 = w2c[(size_t)(k + 1) * D + n];
      float a2 = w2c[(size_t)(k + 8) * D + n], a3 = w2c[(size_t)(k + 9) * D + n];
      bh[kt][ns][0] = pack_h2(__float2half_rn(a0), __float2half_rn(a1));
      bh[kt][ns][1] = pack_h2(__float2half_rn(a2), __float2half_rn(a3));
    }

  // ---- S field computed inline ----
  if (tid < NI3) {
    int J = (w0 - 2 + tid) & (W - 1);
    const float* ab = g_a + (size_t)b * H * W;
    float Sv;
    if (h == H - 1) {
      Sv = fmaxf(ab[(H - 2) * W + J], 0.f);
    } else {
      int hh = (h == H - 2) ? (H - 1) : h;
      float cy = ab[hh * W + J];
      if (hh >= 1) {
        const float* ap = ab + (hh - 1) * W;
#pragma unroll
        for (int k = 0; k < 9; k++) {
          int ww = J + k - 4;
          if (ww >= 0 && ww < W) cy += g_s9[k] * fmaxf(ap[ww], 0.f);
        }
      }
      float u = fmaxf(cy, 0.f);
      int tr = (h == 0) ? (H - 2) : (h == 1 ? -1 : (h <= H - 3 ? h - 2 : H - 3));
      Sv = u + ((tr >= 0) ? fmaxf(ab[tr * W + J], 0.f) : 0.f);
    }
    scol[tid] = Sv;
  }
  if (tid < 128) b2s[tid] = b2g[tid];
  __syncthreads();  // scol ready

  // stage z into Z1 in 2 MLP-9 batches
  stage_batch<9>(smc, xrow, scol, tid, w0, 0);
  stage_batch<9>(smc, xrow, scol, tid, w0, 9);
  __syncthreads();

  const uint32_t aoff = (uint32_t)((lane & 15) * ZB + ((lane >> 4) << 4));

  // ---------- GEMM set 1 on Z1; epilogue writes p into Z2 ----------
#pragma unroll 1
  for (int mt = 0; mt < 9; mt++) {
    const int m0 = mt * 16;
    float accA[2][4] = {};
    gemm_mt(sb + OFF_Z1 + (uint32_t)(m0 * ZB) + aoff, bh, accA);
#pragma unroll
    for (int ns = 0; ns < 2; ns++) {
      int n = n0 + ns * 8 + tig * 2;
      float bb0 = b2s[n], bb1 = b2s[n + 1];
#pragma unroll
      for (int half = 0; half < 2; half++) {
        int r = m0 + g + half * 8;
        int t = r + 1;                       // p[t] = z[t] + v[r]
        if (t > 129) continue;
        float2 zz = rd2h(smc, OFF_Z1, t, n);
        if (!(w0 == 0 && t == 2)) {          // global col 0: p = z
          zz.x += fmaxf(accA[ns][half * 2] + bb0, 0.f);
          zz.y += fmaxf(accA[ns][half * 2 + 1] + bb1, 0.f);
        }
        *(uint32_t*)(smc + OFF_Z2 + t * ZB + n * 2) =
            pack_h2(__float2half_rn(zz.x), __float2half_rn(zz.y));
      }
    }
  }
  __syncthreads();

  // ---------- GEMM set 2 on Z2 (= p), fused q epilogue ----------
  float* qrow = q + ((size_t)(b * H + h) * W) * C;
#pragma unroll 1
  for (int mt = 0; mt < 9; mt++) {
    const int m0 = mt * 16;
    float accA[2][4] = {};
    gemm_mt(sb + OFF_Z2 + (uint32_t)(m0 * ZB) + aoff, bh, accA);
#pragma unroll
    for (int ns = 0; ns < 2; ns++) {
      int n = n0 + ns * 8 + tig * 2;
      float bb0 = b2s[n], bb1 = b2s[n + 1];
#pragma unroll
      for (int half = 0; half < 2; half++) {
        int i = m0 + g + half * 8;
        if (i < 2 || i >= NI3) continue;
        int w = w0 - 2 + i;
        if (w == W - 2) continue;  // r[W-2] discarded by the reference
        float r0 = fmaxf(accA[ns][half * 2] + bb0, 0.f);
        float r1 = fmaxf(accA[ns][half * 2 + 1] + bb1, 0.f);
        if (w == W - 1) {
          float2 p6 = rd2h(smc, OFF_Z2, i - 1, n);
          float2 p7 = rd2h(smc, OFF_Z2, i, n);
          *(float2*)(qrow + (size_t)(W - 2) * C + n) = make_float2(r0 + p6.x, r1 + p6.y);
          *(float2*)(qrow + (size_t)(W - 1) * C + n) = make_float2(p7.x, p7.y);
        } else {
          float2 pm = rd2h(smc, OFF_Z2, i - 1, n);
          *(float2*)(qrow + (size_t)w * C + n) = make_float2(r0 + pm.x, r1 + pm.y);
        }
      }
    }
  }
}

// ============================================================
extern "C" void kernel_launch(void* const* d_in, const int* in_sizes, int n_in,
                              void* d_out, int out_size) {
  (void)in_sizes; (void)n_in; (void)out_size;
  const float* x  = (const float*)d_in[0];
  const float* w1 = (const float*)d_in[1];
  const float* b1 = (const float*)d_in[2];
  const float* w2 = (const float*)d_in[3];
  const float* b2 = (const float*)d_in[4];
  float* q = (float*)d_out;

  cudaFuncSetAttribute(phase3_kernel, cudaFuncAttributeMaxDynamicSharedMemorySize, SM3_BYTES);

  phase1_kernel<<<dim3(W / P1_TW, H, B), 256>>>(x, w1, b1);
  phase3_kernel<<<dim3(W / WT3, H, B), NT3, SM3_BYTES>>>(x, w2, b2, q);
}